// round 3
// baseline (speedup 1.0000x reference)
#include <cuda_runtime.h>

#define BATCH 2
#define NPTS 4096
#define NQ    16384
#define AGG_K 451
#define LDQ   36          // padded row stride (queries dim), mult of 4 for LDS.128

typedef unsigned long long ULL;

// ---------------- scratch (device globals; no allocation allowed) ----------------
__device__ float g_feat[BATCH * NPTS * 448];   // point-major features [b][n][448]
__device__ int   g_gmax[BATCH * 256];          // float-bit max of f3 (post-relu >= 0)
__device__ float g_c1[BATCH * 256];            // folded global-feat bias for r1
__device__ float g_r1o[113 * 1024];            // r1 packed [k/4][256 oc][4]
__device__ float g_r2o[64 * 512];              // r2 packed [k/4][128 oc][4]
__device__ float g_r3o[32 * 256];              // r3 packed [k/4][64 oc][4]

// ---------------- f32x2 packed helpers (sm_103a FFMA2 path) ----------------
__device__ __forceinline__ ULL pk2(float x) {
    ULL r; asm("mov.b64 %0, {%1, %1};" : "=l"(r) : "f"(x)); return r;
}
__device__ __forceinline__ void fma2(ULL& acc, ULL a, ULL b) {
    asm("fma.rn.f32x2 %0, %1, %2, %0;" : "+l"(acc) : "l"(a), "l"(b));
}
__device__ __forceinline__ void upk2(ULL v, float& lo, float& hi) {
    asm("mov.b64 {%0, %1}, %2;" : "=f"(lo), "=f"(hi) : "l"(v));
}

// ---------------- prep: pack regressor weights (k-grouped, oc-coalesced) --------
__global__ void prep_kernel(const float* __restrict__ r1, const float* __restrict__ r2,
                            const float* __restrict__ r3) {
    int stride = gridDim.x * blockDim.x;
    int tid = blockIdx.x * blockDim.x + threadIdx.x;
    if (tid < BATCH * 256) g_gmax[tid] = 0;
    for (int idx = tid; idx < AGG_K * 256; idx += stride) {
        int k = idx >> 8, oc = idx & 255;
        g_r1o[(k >> 2) * 1024 + oc * 4 + (k & 3)] = r1[oc * 707 + k];
    }
    for (int idx = tid; idx < 256 * 128; idx += stride) {
        int k = idx >> 7, oc = idx & 127;
        g_r2o[(k >> 2) * 512 + oc * 4 + (k & 3)] = r2[oc * 256 + k];
    }
    for (int idx = tid; idx < 128 * 64; idx += stride) {
        int k = idx >> 6, oc = idx & 63;
        g_r3o[(k >> 2) * 256 + oc * 4 + (k & 3)] = r3[oc * 128 + k];
    }
}

// ---------------- feature extractor: fused 3-layer 1x1-conv MLP ----------------
__global__ void feat_kernel(const float* __restrict__ opts,
                            const float* __restrict__ w1, const float* __restrict__ b1,
                            const float* __restrict__ w2, const float* __restrict__ b2,
                            const float* __restrict__ w3, const float* __restrict__ b3) {
    extern __shared__ float sm[];
    float* w2t = sm;             // 64 *129 = 8256
    float* w3t = w2t + 8256;     // 128*257 = 32896
    float* f1s = w3t + 32896;    // 64 *33  = 2112
    float* f2s = f1s + 2112;     // 128*33  = 4224
    float* pts = f2s + 4224;     // 96
    int t = threadIdx.x;
    int bb = blockIdx.x >> 7;
    int base = (blockIdx.x & 127) * 32;

    for (int i = t; i < 128 * 64; i += 256) { int oc = i >> 6, k = i & 63; w2t[k * 129 + oc] = w2[i]; }
    for (int i = t; i < 256 * 128; i += 256) { int oc = i >> 7, k = i & 127; w3t[k * 257 + oc] = w3[i]; }
    for (int i = t; i < 96; i += 256) {
        int d = i >> 5, j = i & 31;
        pts[i] = opts[bb * 3 * NPTS + d * NPTS + base + j];
    }
    __syncthreads();

    {   // stage 1: 3 -> 64
        int oc = t & 63, jg = t >> 6;
        float wx = w1[oc * 3], wy = w1[oc * 3 + 1], wz = w1[oc * 3 + 2], bia = b1[oc];
        #pragma unroll
        for (int j = jg * 8; j < jg * 8 + 8; j++) {
            float v = fmaf(wx, pts[j], fmaf(wy, pts[32 + j], fmaf(wz, pts[64 + j], bia)));
            v = fmaxf(v, 0.f);
            f1s[oc * 33 + j] = v;
            g_feat[(bb * NPTS + base + j) * 448 + oc] = v;
        }
    }
    __syncthreads();

    {   // stage 2: 64 -> 128
        int oc = t & 127, half = t >> 7;
        float acc[16];
        float bia = b2[oc];
        #pragma unroll
        for (int i = 0; i < 16; i++) acc[i] = bia;
        for (int k = 0; k < 64; k++) {
            float w = w2t[k * 129 + oc];
            const float* f = &f1s[k * 33 + half * 16];
            #pragma unroll
            for (int i = 0; i < 16; i++) acc[i] = fmaf(w, f[i], acc[i]);
        }
        for (int i = 0; i < 16; i++) {
            float v = fmaxf(acc[i], 0.f);
            int j = half * 16 + i;
            f2s[oc * 33 + j] = v;
            g_feat[(bb * NPTS + base + j) * 448 + 64 + oc] = v;
        }
    }
    __syncthreads();

    {   // stage 3: 128 -> 256 + running max
        int oc = t;
        float acc[32];
        float bia = b3[oc];
        #pragma unroll
        for (int i = 0; i < 32; i++) acc[i] = bia;
        for (int k = 0; k < 128; k++) {
            float w = w3t[k * 257 + oc];
            const float* f = &f2s[k * 33];
            #pragma unroll
            for (int j = 0; j < 32; j++) acc[j] = fmaf(w, f[j], acc[j]);
        }
        float mx = 0.f;
        for (int j = 0; j < 32; j++) {
            float v = fmaxf(acc[j], 0.f);
            g_feat[(bb * NPTS + base + j) * 448 + 192 + oc] = v;
            mx = fmaxf(mx, v);
        }
        atomicMax(&g_gmax[bb * 256 + oc], __float_as_int(mx));
    }
}

// ---------------- fold global feats into r1 bias ----------------
__global__ void c1_kernel(const float* __restrict__ r1, const float* __restrict__ rb1) {
    __shared__ float fms[256];
    int t = threadIdx.x;
    int bb = blockIdx.x >> 3;
    int ocbase = (blockIdx.x & 7) * 32;
    fms[t] = __int_as_float(g_gmax[bb * 256 + t]);
    __syncthreads();
    int oc = ocbase + (t >> 3);
    int seg = t & 7;
    const float* row = r1 + oc * 707 + 451 + seg * 32;
    float s = 0.f;
    #pragma unroll
    for (int i = 0; i < 32; i++) s = fmaf(row[i], fms[seg * 32 + i], s);
    s += __shfl_xor_sync(0xffffffffu, s, 1);
    s += __shfl_xor_sync(0xffffffffu, s, 2);
    s += __shfl_xor_sync(0xffffffffu, s, 4);
    if (seg == 0) g_c1[bb * 256 + oc] = s + rb1[oc];
}

// ---------------- warp top-3 merge ----------------
__device__ __forceinline__ void merge3(float b0, float b1, float b2,
                                       int i0, int i1, int i2, int lane, int sel[3]) {
    int j = 0;
    #pragma unroll
    for (int s = 0; s < 3; s++) {
        float cv = (j == 0) ? b0 : ((j == 1) ? b1 : ((j == 2) ? b2 : 3.4e38f));
        int   ci = (j == 0) ? i0 : ((j == 1) ? i1 : i2);
        float rv = cv; int rl = lane;
        #pragma unroll
        for (int off = 16; off; off >>= 1) {
            float ov = __shfl_down_sync(0xffffffffu, rv, off);
            int   ol = __shfl_down_sync(0xffffffffu, rl, off);
            if (ov < rv) { rv = ov; rl = ol; }
        }
        int wl = __shfl_sync(0xffffffffu, rl, 0);
        sel[s] = __shfl_sync(0xffffffffu, ci, wl);
        if (lane == wl) j++;
    }
}

// ---------------- fused KNN(3) + interpolation + regressor ----------------
// grid = BATCH * (NQ/32), 256 threads; 32 queries/block.
__global__ void __launch_bounds__(256) knnreg_kernel(
        const float* __restrict__ opts, const float* __restrict__ qpts,
        const float* __restrict__ rb2, const float* __restrict__ rb3,
        const float* __restrict__ r4, const float* __restrict__ rb4,
        float* __restrict__ out) {
    extern __shared__ float sm[];
    float* aggs = sm;            // 451*36 = 16236 floats
    float* spt  = sm + 16236;    // 3*4096 = 12288 (dead after KNN)
    float* h1s  = sm + 16236;    // 256*36 = 9216  (overlays spt)
    float* h2s  = sm;            // 128*36 = 4608  (overlays aggs)
    float* h3s  = sm + 4608;     // 64*36  = 2304
    int t = threadIdx.x;
    int bb = blockIdx.x >> 9, tile = blockIdx.x & 511;
    int qbase = tile * 32;

    for (int i = t; i < NPTS; i += 256) {
        spt[i]            = opts[bb * 3 * NPTS + i];
        spt[NPTS + i]     = opts[bb * 3 * NPTS + NPTS + i];
        spt[2 * NPTS + i] = opts[bb * 3 * NPTS + 2 * NPTS + i];
    }
    __syncthreads();
    const float* sx = spt;
    const float* sy = spt + NPTS;
    const float* sz = spt + 2 * NPTS;

    int warp = t >> 5, lane = t & 31;
    int q0 = qbase + warp * 4;
    float qx[4], qy[4], qz[4];
    #pragma unroll
    for (int r = 0; r < 4; r++) {
        qx[r] = qpts[bb * 3 * NQ + q0 + r];
        qy[r] = qpts[bb * 3 * NQ + NQ + q0 + r];
        qz[r] = qpts[bb * 3 * NQ + 2 * NQ + q0 + r];
    }

    float bd[4][3];
    int   bi[4][3];
    #pragma unroll
    for (int r = 0; r < 4; r++)
        #pragma unroll
        for (int s = 0; s < 3; s++) { bd[r][s] = 3.4e38f; bi[r][s] = 0; }

    for (int p = lane; p < NPTS; p += 32) {
        float x = sx[p], y = sy[p], z = sz[p];
        #pragma unroll
        for (int r = 0; r < 4; r++) {
            float dx = qx[r] - x, dy = qy[r] - y, dz = qz[r] - z;
            float dd = fmaf(dx, dx, fmaf(dy, dy, dz * dz));
            if (dd < bd[r][2]) {
                if (dd < bd[r][1]) {
                    bd[r][2] = bd[r][1]; bi[r][2] = bi[r][1];
                    if (dd < bd[r][0]) { bd[r][1] = bd[r][0]; bi[r][1] = bi[r][0]; bd[r][0] = dd; bi[r][0] = p; }
                    else               { bd[r][1] = dd; bi[r][1] = p; }
                } else { bd[r][2] = dd; bi[r][2] = p; }
            }
        }
    }

    #pragma unroll
    for (int r = 0; r < 4; r++) {
        int sel[3];
        merge3(bd[r][0], bd[r][1], bd[r][2], bi[r][0], bi[r][1], bi[r][2], lane, sel);
        int ql = warp * 4 + r;

        float wk[3], wsum = 0.f;
        #pragma unroll
        for (int s = 0; s < 3; s++) {
            int p = sel[s];
            float dx = qx[r] - sx[p], dy = qy[r] - sy[p], dz = qz[r] - sz[p];
            float dist = sqrtf(dx * dx + dy * dy + dz * dz);
            wk[s] = 1.f / (dist + 1e-8f);
            wsum += wk[s];
        }
        float inv = 1.f / wsum;
        wk[0] *= inv; wk[1] *= inv; wk[2] *= inv;

        if (lane == 0) {
            aggs[0 * LDQ + ql] = qx[r];
            aggs[1 * LDQ + ql] = qy[r];
            aggs[2 * LDQ + ql] = qz[r];
        }
        const float* F0 = g_feat + (size_t)(bb * NPTS + sel[0]) * 448;
        const float* F1 = g_feat + (size_t)(bb * NPTS + sel[1]) * 448;
        const float* F2 = g_feat + (size_t)(bb * NPTS + sel[2]) * 448;
        for (int c = lane; c < 448; c += 32)
            aggs[(3 + c) * LDQ + ql] = wk[0] * F0[c] + wk[1] * F1[c] + wk[2] * F2[c];
    }
    __syncthreads();

    int ocb = t & 63;
    int q2 = (t >> 6) * 8;   // this thread's 8 queries start here (4 f32x2 pairs)

    // ---- stage 1: 451 -> 256; 4 ocs x 4 q-pairs per thread ----
    {
        ULL acc[4][4];
        #pragma unroll
        for (int j = 0; j < 4; j++) {
            ULL c = pk2(g_c1[bb * 256 + ocb + 64 * j]);
            #pragma unroll
            for (int i = 0; i < 4; i++) acc[j][i] = c;
        }
        const float4* wbase = (const float4*)g_r1o;
        for (int kg = 0; kg < 112; kg++) {
            float4 w[4];
            #pragma unroll
            for (int j = 0; j < 4; j++) w[j] = wbase[kg * 256 + ocb + 64 * j];
            #pragma unroll
            for (int kk = 0; kk < 4; kk++) {
                const float* arow = aggs + (kg * 4 + kk) * LDQ + q2;
                ulonglong2 aA = *(const ulonglong2*)(arow);
                ulonglong2 aB = *(const ulonglong2*)(arow + 4);
                #pragma unroll
                for (int j = 0; j < 4; j++) {
                    float ws = kk == 0 ? w[j].x : kk == 1 ? w[j].y : kk == 2 ? w[j].z : w[j].w;
                    ULL wv = pk2(ws);
                    fma2(acc[j][0], wv, aA.x);
                    fma2(acc[j][1], wv, aA.y);
                    fma2(acc[j][2], wv, aB.x);
                    fma2(acc[j][3], wv, aB.y);
                }
            }
        }
        #pragma unroll
        for (int k = 448; k < 451; k++) {
            const float* arow = aggs + k * LDQ + q2;
            ulonglong2 aA = *(const ulonglong2*)(arow);
            ulonglong2 aB = *(const ulonglong2*)(arow + 4);
            #pragma unroll
            for (int j = 0; j < 4; j++) {
                ULL wv = pk2(g_r1o[112 * 1024 + (ocb + 64 * j) * 4 + (k - 448)]);
                fma2(acc[j][0], wv, aA.x);
                fma2(acc[j][1], wv, aA.y);
                fma2(acc[j][2], wv, aB.x);
                fma2(acc[j][3], wv, aB.y);
            }
        }
        __syncthreads();   // all aggs reads done before h1s (spt region) is written? h1s!=aggs, but keep barrier before overlay writes
        #pragma unroll
        for (int j = 0; j < 4; j++) {
            float* hrow = h1s + (ocb + 64 * j) * LDQ + q2;
            #pragma unroll
            for (int i = 0; i < 4; i++) {
                float lo, hi; upk2(acc[j][i], lo, hi);
                hrow[2 * i]     = fmaxf(lo, 0.f);
                hrow[2 * i + 1] = fmaxf(hi, 0.f);
            }
        }
    }
    __syncthreads();

    // ---- stage 2: 256 -> 128; 2 ocs x 4 q-pairs ----
    {
        ULL acc[2][4];
        #pragma unroll
        for (int j = 0; j < 2; j++) {
            ULL c = pk2(rb2[ocb + 64 * j]);
            #pragma unroll
            for (int i = 0; i < 4; i++) acc[j][i] = c;
        }
        const float4* wbase = (const float4*)g_r2o;
        for (int kg = 0; kg < 64; kg++) {
            float4 w[2];
            #pragma unroll
            for (int j = 0; j < 2; j++) w[j] = wbase[kg * 128 + ocb + 64 * j];
            #pragma unroll
            for (int kk = 0; kk < 4; kk++) {
                const float* arow = h1s + (kg * 4 + kk) * LDQ + q2;
                ulonglong2 aA = *(const ulonglong2*)(arow);
                ulonglong2 aB = *(const ulonglong2*)(arow + 4);
                #pragma unroll
                for (int j = 0; j < 2; j++) {
                    float ws = kk == 0 ? w[j].x : kk == 1 ? w[j].y : kk == 2 ? w[j].z : w[j].w;
                    ULL wv = pk2(ws);
                    fma2(acc[j][0], wv, aA.x);
                    fma2(acc[j][1], wv, aA.y);
                    fma2(acc[j][2], wv, aB.x);
                    fma2(acc[j][3], wv, aB.y);
                }
            }
        }
        #pragma unroll
        for (int j = 0; j < 2; j++) {
            float* hrow = h2s + (ocb + 64 * j) * LDQ + q2;
            #pragma unroll
            for (int i = 0; i < 4; i++) {
                float lo, hi; upk2(acc[j][i], lo, hi);
                hrow[2 * i]     = fmaxf(lo, 0.f);
                hrow[2 * i + 1] = fmaxf(hi, 0.f);
            }
        }
    }
    __syncthreads();

    // ---- stage 3: 128 -> 64; 1 oc x 4 q-pairs ----
    {
        ULL acc[4];
        ULL c = pk2(rb3[ocb]);
        #pragma unroll
        for (int i = 0; i < 4; i++) acc[i] = c;
        const float4* wbase = (const float4*)g_r3o;
        for (int kg = 0; kg < 32; kg++) {
            float4 w = wbase[kg * 64 + ocb];
            #pragma unroll
            for (int kk = 0; kk < 4; kk++) {
                const float* arow = h2s + (kg * 4 + kk) * LDQ + q2;
                ulonglong2 aA = *(const ulonglong2*)(arow);
                ulonglong2 aB = *(const ulonglong2*)(arow + 4);
                float ws = kk == 0 ? w.x : kk == 1 ? w.y : kk == 2 ? w.z : w.w;
                ULL wv = pk2(ws);
                fma2(acc[0], wv, aA.x);
                fma2(acc[1], wv, aA.y);
                fma2(acc[2], wv, aB.x);
                fma2(acc[3], wv, aB.y);
            }
        }
        float* hrow = h3s + ocb * LDQ + q2;
        #pragma unroll
        for (int i = 0; i < 4; i++) {
            float lo, hi; upk2(acc[i], lo, hi);
            hrow[2 * i]     = fmaxf(lo, 0.f);
            hrow[2 * i + 1] = fmaxf(hi, 0.f);
        }
    }
    __syncthreads();

    // ---- stage 4: 64 -> 1 ----
    {
        int w4 = t >> 5, l4 = t & 31;
        int qloc = w4 * 4 + (l4 >> 3);
        int c0 = l4 & 7;
        float p = 0.f;
        #pragma unroll
        for (int jj = 0; jj < 8; jj++) {
            int c = c0 + jj * 8;
            p = fmaf(r4[c], h3s[c * LDQ + qloc], p);
        }
        p += __shfl_xor_sync(0xffffffffu, p, 1);
        p += __shfl_xor_sync(0xffffffffu, p, 2);
        p += __shfl_xor_sync(0xffffffffu, p, 4);
        if ((l4 & 7) == 0) out[bb * NQ + qbase + qloc] = p + rb4[0];
    }
}

// ---------------- launch ----------------
extern "C" void kernel_launch(void* const* d_in, const int* in_sizes, int n_in,
                              void* d_out, int out_size) {
    const float* opts = (const float*)d_in[0];
    const float* qpts = (const float*)d_in[1];
    const float* w1 = (const float*)d_in[2];
    const float* b1 = (const float*)d_in[3];
    const float* w2 = (const float*)d_in[4];
    const float* b2 = (const float*)d_in[5];
    const float* w3 = (const float*)d_in[6];
    const float* b3 = (const float*)d_in[7];
    const float* r1 = (const float*)d_in[8];
    const float* rb1 = (const float*)d_in[9];
    const float* r2 = (const float*)d_in[10];
    const float* rb2 = (const float*)d_in[11];
    const float* r3 = (const float*)d_in[12];
    const float* rb3 = (const float*)d_in[13];
    const float* r4 = (const float*)d_in[14];
    const float* rb4 = (const float*)d_in[15];
    float* out = (float*)d_out;

    cudaFuncSetAttribute(feat_kernel, cudaFuncAttributeMaxDynamicSharedMemorySize, 190336);
    cudaFuncSetAttribute(knnreg_kernel, cudaFuncAttributeMaxDynamicSharedMemorySize, 114096);

    prep_kernel<<<64, 256>>>(r1, r2, r3);
    feat_kernel<<<BATCH * (NPTS / 32), 256, 190336>>>(opts, w1, b1, w2, b2, w3, b3);
    c1_kernel<<<BATCH * 8, 256>>>(r1, rb1);
    knnreg_kernel<<<BATCH * (NQ / 32), 256, 114096>>>(opts, qpts, rb2, rb3, r4, rb4, out);
}

// round 4
// speedup vs baseline: 1.8283x; 1.8283x over previous
#include <cuda_runtime.h>

#define BATCH 2
#define NPTS 4096
#define NQ    16384
#define AGG_K 451
#define LDQ   36
#define CHUNK 512

typedef unsigned long long ULL;

// ---------------- scratch ----------------
__device__ float g_feat[BATCH * NPTS * 448];
__device__ int   g_gmax[BATCH * 256];
__device__ float g_c1[BATCH * 256];
__device__ float g_r1o[113 * 1024];   // [k/4][256 oc][4]
__device__ float g_r2o[64 * 512];     // [k/4][128 oc][4]
__device__ float g_r3o[32 * 256];     // [k/4][64 oc][4]

// ---------------- f32x2 helpers ----------------
__device__ __forceinline__ ULL pk2(float x) {
    ULL r; asm("mov.b64 %0, {%1, %1};" : "=l"(r) : "f"(x)); return r;
}
__device__ __forceinline__ void fma2(ULL& acc, ULL a, ULL b) {
    asm("fma.rn.f32x2 %0, %1, %2, %0;" : "+l"(acc) : "l"(a), "l"(b));
}
__device__ __forceinline__ void upk2(ULL v, float& lo, float& hi) {
    asm("mov.b64 {%0, %1}, %2;" : "=f"(lo), "=f"(hi) : "l"(v));
}

// ---------------- prep ----------------
__global__ void prep_kernel(const float* __restrict__ r1, const float* __restrict__ r2,
                            const float* __restrict__ r3) {
    int stride = gridDim.x * blockDim.x;
    int tid = blockIdx.x * blockDim.x + threadIdx.x;
    if (tid < BATCH * 256) g_gmax[tid] = 0;
    for (int idx = tid; idx < AGG_K * 256; idx += stride) {
        int k = idx >> 8, oc = idx & 255;
        g_r1o[(k >> 2) * 1024 + oc * 4 + (k & 3)] = r1[oc * 707 + k];
    }
    for (int idx = tid; idx < 256 * 128; idx += stride) {
        int k = idx >> 7, oc = idx & 127;
        g_r2o[(k >> 2) * 512 + oc * 4 + (k & 3)] = r2[oc * 256 + k];
    }
    for (int idx = tid; idx < 128 * 64; idx += stride) {
        int k = idx >> 6, oc = idx & 63;
        g_r3o[(k >> 2) * 256 + oc * 4 + (k & 3)] = r3[oc * 128 + k];
    }
}

// ---------------- feature extractor ----------------
__global__ void feat_kernel(const float* __restrict__ opts,
                            const float* __restrict__ w1, const float* __restrict__ b1,
                            const float* __restrict__ w2, const float* __restrict__ b2,
                            const float* __restrict__ w3, const float* __restrict__ b3) {
    extern __shared__ float sm[];
    float* w2t = sm;             // 64*129
    float* w3t = w2t + 8256;     // 128*257
    float* f1s = w3t + 32896;    // 64*33
    float* f2s = f1s + 2112;     // 128*33
    float* pts = f2s + 4224;     // 96
    int t = threadIdx.x;
    int bb = blockIdx.x >> 7;
    int base = (blockIdx.x & 127) * 32;

    for (int i = t; i < 128 * 64; i += 256) { int oc = i >> 6, k = i & 63; w2t[k * 129 + oc] = w2[i]; }
    for (int i = t; i < 256 * 128; i += 256) { int oc = i >> 7, k = i & 127; w3t[k * 257 + oc] = w3[i]; }
    for (int i = t; i < 96; i += 256) {
        int d = i >> 5, j = i & 31;
        pts[i] = opts[bb * 3 * NPTS + d * NPTS + base + j];
    }
    __syncthreads();

    {   // 3 -> 64
        int oc = t & 63, jg = t >> 6;
        float wx = w1[oc * 3], wy = w1[oc * 3 + 1], wz = w1[oc * 3 + 2], bia = b1[oc];
        #pragma unroll
        for (int j = jg * 8; j < jg * 8 + 8; j++) {
            float v = fmaf(wx, pts[j], fmaf(wy, pts[32 + j], fmaf(wz, pts[64 + j], bia)));
            v = fmaxf(v, 0.f);
            f1s[oc * 33 + j] = v;
            g_feat[(bb * NPTS + base + j) * 448 + oc] = v;
        }
    }
    __syncthreads();

    {   // 64 -> 128
        int oc = t & 127, half = t >> 7;
        float acc[16];
        float bia = b2[oc];
        #pragma unroll
        for (int i = 0; i < 16; i++) acc[i] = bia;
        for (int k = 0; k < 64; k++) {
            float w = w2t[k * 129 + oc];
            const float* f = &f1s[k * 33 + half * 16];
            #pragma unroll
            for (int i = 0; i < 16; i++) acc[i] = fmaf(w, f[i], acc[i]);
        }
        for (int i = 0; i < 16; i++) {
            float v = fmaxf(acc[i], 0.f);
            int j = half * 16 + i;
            f2s[oc * 33 + j] = v;
            g_feat[(bb * NPTS + base + j) * 448 + 64 + oc] = v;
        }
    }
    __syncthreads();

    {   // 128 -> 256 + max
        int oc = t;
        float acc[32];
        float bia = b3[oc];
        #pragma unroll
        for (int i = 0; i < 32; i++) acc[i] = bia;
        for (int k = 0; k < 128; k++) {
            float w = w3t[k * 257 + oc];
            const float* f = &f2s[k * 33];
            #pragma unroll
            for (int j = 0; j < 32; j++) acc[j] = fmaf(w, f[j], acc[j]);
        }
        float mx = 0.f;
        for (int j = 0; j < 32; j++) {
            float v = fmaxf(acc[j], 0.f);
            g_feat[(bb * NPTS + base + j) * 448 + 192 + oc] = v;
            mx = fmaxf(mx, v);
        }
        atomicMax(&g_gmax[bb * 256 + oc], __float_as_int(mx));
    }
}

// ---------------- fold global feats into r1 bias ----------------
__global__ void c1_kernel(const float* __restrict__ r1, const float* __restrict__ rb1) {
    __shared__ float fms[256];
    int t = threadIdx.x;
    int bb = blockIdx.x >> 3;
    int ocbase = (blockIdx.x & 7) * 32;
    fms[t] = __int_as_float(g_gmax[bb * 256 + t]);
    __syncthreads();
    int oc = ocbase + (t >> 3);
    int seg = t & 7;
    const float* row = r1 + oc * 707 + 451 + seg * 32;
    float s = 0.f;
    #pragma unroll
    for (int i = 0; i < 32; i++) s = fmaf(row[i], fms[seg * 32 + i], s);
    s += __shfl_xor_sync(0xffffffffu, s, 1);
    s += __shfl_xor_sync(0xffffffffu, s, 2);
    s += __shfl_xor_sync(0xffffffffu, s, 4);
    if (seg == 0) g_c1[bb * 256 + oc] = s + rb1[oc];
}

// ---------------- warp top-3 merge returning dists ----------------
__device__ __forceinline__ void merge3d(float b0, float b1, float b2,
                                        int i0, int i1, int i2, int lane,
                                        int sel[3], float seld[3]) {
    int j = 0;
    #pragma unroll
    for (int s = 0; s < 3; s++) {
        float cv = (j == 0) ? b0 : ((j == 1) ? b1 : ((j == 2) ? b2 : 3.4e38f));
        int   ci = (j == 0) ? i0 : ((j == 1) ? i1 : i2);
        float rv = cv; int rl = lane;
        #pragma unroll
        for (int off = 16; off; off >>= 1) {
            float ov = __shfl_down_sync(0xffffffffu, rv, off);
            int   ol = __shfl_down_sync(0xffffffffu, rl, off);
            if (ov < rv) { rv = ov; rl = ol; }
        }
        int wl = __shfl_sync(0xffffffffu, rl, 0);
        seld[s] = __shfl_sync(0xffffffffu, rv, 0);
        sel[s]  = __shfl_sync(0xffffffffu, ci, wl);
        if (lane == wl) j++;
    }
}

// ---------------- fused KNN(3) + interpolation + regressor ----------------
// grid = BATCH*(NQ/32), 256 threads, 3 CTAs/SM (71 KB smem)
__global__ void __launch_bounds__(256, 3) knnreg_kernel(
        const float* __restrict__ opts, const float* __restrict__ qpts,
        const float* __restrict__ rb2, const float* __restrict__ rb3,
        const float* __restrict__ r4, const float* __restrict__ rb4,
        float* __restrict__ out) {
    extern __shared__ float sm[];
    float* aggs = sm;            // 451*36 = 16236
    float* cx   = sm + 16236;    // 512
    float* cy   = cx + CHUNK;    // 512
    float* cz   = cy + CHUNK;    // 512  -> total 17772 floats = 71088 B
    float* h1s  = sm;            // 256*36 = 9216 (overlays aggs after stage1)
    float* h2s  = sm + 9216;     // 128*36 = 4608
    float* h3s  = sm + 13824;    // 64*36  = 2304
    int t = threadIdx.x;
    int bb = blockIdx.x >> 9, tile = blockIdx.x & 511;
    int qbase = tile * 32;
    int warp = t >> 5, lane = t & 31;

    int q0 = qbase + warp * 4;
    float qx[4], qy[4], qz[4];
    #pragma unroll
    for (int r = 0; r < 4; r++) {
        qx[r] = qpts[bb * 3 * NQ + q0 + r];
        qy[r] = qpts[bb * 3 * NQ + NQ + q0 + r];
        qz[r] = qpts[bb * 3 * NQ + 2 * NQ + q0 + r];
    }

    float bd[4][3];
    int   bi[4][3];
    #pragma unroll
    for (int r = 0; r < 4; r++)
        #pragma unroll
        for (int s = 0; s < 3; s++) { bd[r][s] = 3.4e38f; bi[r][s] = 0; }

    const float* obase = opts + bb * 3 * NPTS;
    for (int ch = 0; ch < NPTS / CHUNK; ch++) {
        __syncthreads();
        for (int i = t; i < CHUNK; i += 256) {
            cx[i] = obase[ch * CHUNK + i];
            cy[i] = obase[NPTS + ch * CHUNK + i];
            cz[i] = obase[2 * NPTS + ch * CHUNK + i];
        }
        __syncthreads();
        int gb = ch * CHUNK;
        for (int p = lane; p < CHUNK; p += 32) {
            float x = cx[p], y = cy[p], z = cz[p];
            #pragma unroll
            for (int r = 0; r < 4; r++) {
                float dx = qx[r] - x, dy = qy[r] - y, dz = qz[r] - z;
                float dd = fmaf(dx, dx, fmaf(dy, dy, dz * dz));
                if (dd < bd[r][2]) {
                    if (dd < bd[r][1]) {
                        bd[r][2] = bd[r][1]; bi[r][2] = bi[r][1];
                        if (dd < bd[r][0]) { bd[r][1] = bd[r][0]; bi[r][1] = bi[r][0]; bd[r][0] = dd; bi[r][0] = gb + p; }
                        else               { bd[r][1] = dd; bi[r][1] = gb + p; }
                    } else { bd[r][2] = dd; bi[r][2] = gb + p; }
                }
            }
        }
    }
    __syncthreads();

    #pragma unroll
    for (int r = 0; r < 4; r++) {
        int sel[3]; float seld[3];
        merge3d(bd[r][0], bd[r][1], bd[r][2], bi[r][0], bi[r][1], bi[r][2], lane, sel, seld);
        int ql = warp * 4 + r;

        float wk0 = 1.f / (sqrtf(seld[0]) + 1e-8f);
        float wk1 = 1.f / (sqrtf(seld[1]) + 1e-8f);
        float wk2 = 1.f / (sqrtf(seld[2]) + 1e-8f);
        float inv = 1.f / (wk0 + wk1 + wk2);
        wk0 *= inv; wk1 *= inv; wk2 *= inv;

        if (lane == 0) {
            aggs[0 * LDQ + ql] = qx[r];
            aggs[1 * LDQ + ql] = qy[r];
            aggs[2 * LDQ + ql] = qz[r];
        }
        const float4* F0 = (const float4*)(g_feat + (size_t)(bb * NPTS + sel[0]) * 448);
        const float4* F1 = (const float4*)(g_feat + (size_t)(bb * NPTS + sel[1]) * 448);
        const float4* F2 = (const float4*)(g_feat + (size_t)(bb * NPTS + sel[2]) * 448);
        for (int c4 = lane; c4 < 112; c4 += 32) {
            float4 a = F0[c4], b = F1[c4], c = F2[c4];
            int cc = 3 + c4 * 4;
            aggs[(cc + 0) * LDQ + ql] = wk0 * a.x + wk1 * b.x + wk2 * c.x;
            aggs[(cc + 1) * LDQ + ql] = wk0 * a.y + wk1 * b.y + wk2 * c.y;
            aggs[(cc + 2) * LDQ + ql] = wk0 * a.z + wk1 * b.z + wk2 * c.z;
            aggs[(cc + 3) * LDQ + ql] = wk0 * a.w + wk1 * b.w + wk2 * c.w;
        }
    }
    __syncthreads();

    int ocb = t & 63;
    int q2 = (t >> 6) * 8;

    // ---- stage 1: 451 -> 256; 4 ocs x 4 q-pairs, weight prefetch ----
    {
        ULL acc[4][4];
        #pragma unroll
        for (int j = 0; j < 4; j++) {
            ULL c = pk2(g_c1[bb * 256 + ocb + 64 * j]);
            #pragma unroll
            for (int i = 0; i < 4; i++) acc[j][i] = c;
        }
        const float4* wb = (const float4*)g_r1o;
        float4 w0 = wb[ocb], w1 = wb[ocb + 64], w2 = wb[ocb + 128], w3 = wb[ocb + 192];
        for (int kg = 0; kg < 112; kg++) {
            int kn = (kg < 111) ? kg + 1 : kg;
            float4 n0 = wb[kn * 256 + ocb];
            float4 n1 = wb[kn * 256 + ocb + 64];
            float4 n2 = wb[kn * 256 + ocb + 128];
            float4 n3 = wb[kn * 256 + ocb + 192];
            #pragma unroll
            for (int kk = 0; kk < 4; kk++) {
                const float* arow = aggs + (kg * 4 + kk) * LDQ + q2;
                ulonglong2 aA = *(const ulonglong2*)(arow);
                ulonglong2 aB = *(const ulonglong2*)(arow + 4);
                float s0 = kk == 0 ? w0.x : kk == 1 ? w0.y : kk == 2 ? w0.z : w0.w;
                float s1 = kk == 0 ? w1.x : kk == 1 ? w1.y : kk == 2 ? w1.z : w1.w;
                float s2 = kk == 0 ? w2.x : kk == 1 ? w2.y : kk == 2 ? w2.z : w2.w;
                float s3 = kk == 0 ? w3.x : kk == 1 ? w3.y : kk == 2 ? w3.z : w3.w;
                ULL v0 = pk2(s0), v1 = pk2(s1), v2 = pk2(s2), v3 = pk2(s3);
                fma2(acc[0][0], v0, aA.x); fma2(acc[0][1], v0, aA.y);
                fma2(acc[0][2], v0, aB.x); fma2(acc[0][3], v0, aB.y);
                fma2(acc[1][0], v1, aA.x); fma2(acc[1][1], v1, aA.y);
                fma2(acc[1][2], v1, aB.x); fma2(acc[1][3], v1, aB.y);
                fma2(acc[2][0], v2, aA.x); fma2(acc[2][1], v2, aA.y);
                fma2(acc[2][2], v2, aB.x); fma2(acc[2][3], v2, aB.y);
                fma2(acc[3][0], v3, aA.x); fma2(acc[3][1], v3, aA.y);
                fma2(acc[3][2], v3, aB.x); fma2(acc[3][3], v3, aB.y);
            }
            w0 = n0; w1 = n1; w2 = n2; w3 = n3;
        }
        #pragma unroll
        for (int k = 448; k < 451; k++) {
            const float* arow = aggs + k * LDQ + q2;
            ulonglong2 aA = *(const ulonglong2*)(arow);
            ulonglong2 aB = *(const ulonglong2*)(arow + 4);
            #pragma unroll
            for (int j = 0; j < 4; j++) {
                ULL wv = pk2(g_r1o[112 * 1024 + (ocb + 64 * j) * 4 + (k - 448)]);
                fma2(acc[j][0], wv, aA.x);
                fma2(acc[j][1], wv, aA.y);
                fma2(acc[j][2], wv, aB.x);
                fma2(acc[j][3], wv, aB.y);
            }
        }
        __syncthreads();   // all aggs reads complete before overlay writes
        #pragma unroll
        for (int j = 0; j < 4; j++) {
            float* hrow = h1s + (ocb + 64 * j) * LDQ + q2;
            #pragma unroll
            for (int i = 0; i < 4; i++) {
                float lo, hi; upk2(acc[j][i], lo, hi);
                hrow[2 * i]     = fmaxf(lo, 0.f);
                hrow[2 * i + 1] = fmaxf(hi, 0.f);
            }
        }
    }
    __syncthreads();

    // ---- stage 2: 256 -> 128; 2 ocs x 4 q-pairs, prefetch ----
    {
        ULL acc[2][4];
        #pragma unroll
        for (int j = 0; j < 2; j++) {
            ULL c = pk2(rb2[ocb + 64 * j]);
            #pragma unroll
            for (int i = 0; i < 4; i++) acc[j][i] = c;
        }
        const float4* wb = (const float4*)g_r2o;
        float4 w0 = wb[ocb], w1 = wb[ocb + 64];
        for (int kg = 0; kg < 64; kg++) {
            int kn = (kg < 63) ? kg + 1 : kg;
            float4 n0 = wb[kn * 128 + ocb];
            float4 n1 = wb[kn * 128 + ocb + 64];
            #pragma unroll
            for (int kk = 0; kk < 4; kk++) {
                const float* arow = h1s + (kg * 4 + kk) * LDQ + q2;
                ulonglong2 aA = *(const ulonglong2*)(arow);
                ulonglong2 aB = *(const ulonglong2*)(arow + 4);
                float s0 = kk == 0 ? w0.x : kk == 1 ? w0.y : kk == 2 ? w0.z : w0.w;
                float s1 = kk == 0 ? w1.x : kk == 1 ? w1.y : kk == 2 ? w1.z : w1.w;
                ULL v0 = pk2(s0), v1 = pk2(s1);
                fma2(acc[0][0], v0, aA.x); fma2(acc[0][1], v0, aA.y);
                fma2(acc[0][2], v0, aB.x); fma2(acc[0][3], v0, aB.y);
                fma2(acc[1][0], v1, aA.x); fma2(acc[1][1], v1, aA.y);
                fma2(acc[1][2], v1, aB.x); fma2(acc[1][3], v1, aB.y);
            }
            w0 = n0; w1 = n1;
        }
        __syncthreads();
        #pragma unroll
        for (int j = 0; j < 2; j++) {
            float* hrow = h2s + (ocb + 64 * j) * LDQ + q2;
            #pragma unroll
            for (int i = 0; i < 4; i++) {
                float lo, hi; upk2(acc[j][i], lo, hi);
                hrow[2 * i]     = fmaxf(lo, 0.f);
                hrow[2 * i + 1] = fmaxf(hi, 0.f);
            }
        }
    }
    __syncthreads();

    // ---- stage 3: 128 -> 64 ----
    {
        ULL acc[4];
        ULL c = pk2(rb3[ocb]);
        #pragma unroll
        for (int i = 0; i < 4; i++) acc[i] = c;
        const float4* wb = (const float4*)g_r3o;
        for (int kg = 0; kg < 32; kg++) {
            float4 w = wb[kg * 64 + ocb];
            #pragma unroll
            for (int kk = 0; kk < 4; kk++) {
                const float* arow = h2s + (kg * 4 + kk) * LDQ + q2;
                ulonglong2 aA = *(const ulonglong2*)(arow);
                ulonglong2 aB = *(const ulonglong2*)(arow + 4);
                float ws = kk == 0 ? w.x : kk == 1 ? w.y : kk == 2 ? w.z : w.w;
                ULL wv = pk2(ws);
                fma2(acc[0], wv, aA.x);
                fma2(acc[1], wv, aA.y);
                fma2(acc[2], wv, aB.x);
                fma2(acc[3], wv, aB.y);
            }
        }
        float* hrow = h3s + ocb * LDQ + q2;
        #pragma unroll
        for (int i = 0; i < 4; i++) {
            float lo, hi; upk2(acc[i], lo, hi);
            hrow[2 * i]     = fmaxf(lo, 0.f);
            hrow[2 * i + 1] = fmaxf(hi, 0.f);
        }
    }
    __syncthreads();

    // ---- stage 4: 64 -> 1 ----
    {
        int w4 = t >> 5, l4 = t & 31;
        int qloc = w4 * 4 + (l4 >> 3);
        int c0 = l4 & 7;
        float p = 0.f;
        #pragma unroll
        for (int jj = 0; jj < 8; jj++) {
            int c = c0 + jj * 8;
            p = fmaf(r4[c], h3s[c * LDQ + qloc], p);
        }
        p += __shfl_xor_sync(0xffffffffu, p, 1);
        p += __shfl_xor_sync(0xffffffffu, p, 2);
        p += __shfl_xor_sync(0xffffffffu, p, 4);
        if ((l4 & 7) == 0) out[bb * NQ + qbase + qloc] = p + rb4[0];
    }
}

// ---------------- launch ----------------
extern "C" void kernel_launch(void* const* d_in, const int* in_sizes, int n_in,
                              void* d_out, int out_size) {
    const float* opts = (const float*)d_in[0];
    const float* qpts = (const float*)d_in[1];
    const float* w1 = (const float*)d_in[2];
    const float* b1 = (const float*)d_in[3];
    const float* w2 = (const float*)d_in[4];
    const float* b2 = (const float*)d_in[5];
    const float* w3 = (const float*)d_in[6];
    const float* b3 = (const float*)d_in[7];
    const float* r1 = (const float*)d_in[8];
    const float* rb1 = (const float*)d_in[9];
    const float* r2 = (const float*)d_in[10];
    const float* rb2 = (const float*)d_in[11];
    const float* r3 = (const float*)d_in[12];
    const float* rb3 = (const float*)d_in[13];
    const float* r4 = (const float*)d_in[14];
    const float* rb4 = (const float*)d_in[15];
    float* out = (float*)d_out;

    cudaFuncSetAttribute(feat_kernel, cudaFuncAttributeMaxDynamicSharedMemorySize, 190336);
    cudaFuncSetAttribute(knnreg_kernel, cudaFuncAttributeMaxDynamicSharedMemorySize, 71088);

    prep_kernel<<<64, 256>>>(r1, r2, r3);
    feat_kernel<<<BATCH * (NPTS / 32), 256, 190336>>>(opts, w1, b1, w2, b2, w3, b3);
    c1_kernel<<<BATCH * 8, 256>>>(r1, rb1);
    knnreg_kernel<<<BATCH * (NQ / 32), 256, 71088>>>(opts, qpts, rb2, rb3, r4, rb4, out);
}

// round 8
// speedup vs baseline: 2.2930x; 1.2542x over previous
#include <cuda_runtime.h>

#define BATCH 2
#define NPTS 4096
#define NQ    16384
#define CHUNK 512
#define LDQ   36

typedef unsigned long long ULL;

// ---------------- scratch ----------------
__device__ float g_feat[BATCH * NPTS * 448];   // [b][p][448] post-relu features
__device__ float g_G[BATCH * NPTS * 256];      // [b][p][256]  feat @ W1[3:451]
__device__ int   g_gmax[BATCH * 256];
__device__ float g_c1[BATCH * 256];            // rb1 + W1[451:]@globalfeat
__device__ float g_w1q[256 * 4];               // [oc]{w1x,w1y,w1z,0}
__device__ float g_rG[112 * 1024];             // W1[3:451] packed [c/4][256 oc][4]
__device__ float g_r2o[64 * 512];              // [k/4][128 oc][4]
__device__ float g_r3o[32 * 256];              // [k/4][64 oc][4]

// ---------------- f32x2 helpers ----------------
__device__ __forceinline__ ULL pk2(float x) {
    ULL r; asm("mov.b64 %0, {%1, %1};" : "=l"(r) : "f"(x)); return r;
}
__device__ __forceinline__ void fma2(ULL& acc, ULL a, ULL b) {
    asm("fma.rn.f32x2 %0, %1, %2, %0;" : "+l"(acc) : "l"(a), "l"(b));
}
__device__ __forceinline__ void upk2(ULL v, float& lo, float& hi) {
    asm("mov.b64 {%0, %1}, %2;" : "=f"(lo), "=f"(hi) : "l"(v));
}

// ---------------- prep ----------------
__global__ void prep_kernel(const float* __restrict__ r1, const float* __restrict__ r2,
                            const float* __restrict__ r3) {
    int stride = gridDim.x * blockDim.x;
    int tid = blockIdx.x * blockDim.x + threadIdx.x;
    if (tid < BATCH * 256) g_gmax[tid] = 0;
    for (int idx = tid; idx < 448 * 256; idx += stride) {
        int c = idx >> 8, oc = idx & 255;
        g_rG[(c >> 2) * 1024 + oc * 4 + (c & 3)] = r1[oc * 707 + 3 + c];
    }
    for (int idx = tid; idx < 256 * 4; idx += stride) {
        int oc = idx >> 2, d = idx & 3;
        g_w1q[idx] = (d < 3) ? r1[oc * 707 + d] : 0.f;
    }
    for (int idx = tid; idx < 256 * 128; idx += stride) {
        int k = idx >> 7, oc = idx & 127;
        g_r2o[(k >> 2) * 512 + oc * 4 + (k & 3)] = r2[oc * 256 + k];
    }
    for (int idx = tid; idx < 128 * 64; idx += stride) {
        int k = idx >> 6, oc = idx & 63;
        g_r3o[(k >> 2) * 256 + oc * 4 + (k & 3)] = r3[oc * 128 + k];
    }
}

// ---------------- feature extractor ----------------
__global__ void feat_kernel(const float* __restrict__ opts,
                            const float* __restrict__ w1, const float* __restrict__ b1,
                            const float* __restrict__ w2, const float* __restrict__ b2,
                            const float* __restrict__ w3, const float* __restrict__ b3) {
    extern __shared__ float sm[];
    float* w2t = sm;             // 64*129
    float* w3t = w2t + 8256;     // 128*257
    float* f1s = w3t + 32896;    // 64*33
    float* f2s = f1s + 2112;     // 128*33
    float* pts = f2s + 4224;     // 96
    int t = threadIdx.x;
    int bb = blockIdx.x >> 7;
    int base = (blockIdx.x & 127) * 32;

    for (int i = t; i < 128 * 64; i += 256) { int oc = i >> 6, k = i & 63; w2t[k * 129 + oc] = w2[i]; }
    for (int i = t; i < 256 * 128; i += 256) { int oc = i >> 7, k = i & 127; w3t[k * 257 + oc] = w3[i]; }
    for (int i = t; i < 96; i += 256) {
        int d = i >> 5, j = i & 31;
        pts[i] = opts[bb * 3 * NPTS + d * NPTS + base + j];
    }
    __syncthreads();

    {   // 3 -> 64
        int oc = t & 63, jg = t >> 6;
        float wx = w1[oc * 3], wy = w1[oc * 3 + 1], wz = w1[oc * 3 + 2], bia = b1[oc];
        #pragma unroll
        for (int j = jg * 8; j < jg * 8 + 8; j++) {
            float v = fmaf(wx, pts[j], fmaf(wy, pts[32 + j], fmaf(wz, pts[64 + j], bia)));
            v = fmaxf(v, 0.f);
            f1s[oc * 33 + j] = v;
            g_feat[(bb * NPTS + base + j) * 448 + oc] = v;
        }
    }
    __syncthreads();

    {   // 64 -> 128
        int oc = t & 127, half = t >> 7;
        float acc[16];
        float bia = b2[oc];
        #pragma unroll
        for (int i = 0; i < 16; i++) acc[i] = bia;
        for (int k = 0; k < 64; k++) {
            float w = w2t[k * 129 + oc];
            const float* f = &f1s[k * 33 + half * 16];
            #pragma unroll
            for (int i = 0; i < 16; i++) acc[i] = fmaf(w, f[i], acc[i]);
        }
        for (int i = 0; i < 16; i++) {
            float v = fmaxf(acc[i], 0.f);
            int j = half * 16 + i;
            f2s[oc * 33 + j] = v;
            g_feat[(bb * NPTS + base + j) * 448 + 64 + oc] = v;
        }
    }
    __syncthreads();

    {   // 128 -> 256 + max
        int oc = t;
        float acc[32];
        float bia = b3[oc];
        #pragma unroll
        for (int i = 0; i < 32; i++) acc[i] = bia;
        for (int k = 0; k < 128; k++) {
            float w = w3t[k * 257 + oc];
            const float* f = &f2s[k * 33];
            #pragma unroll
            for (int j = 0; j < 32; j++) acc[j] = fmaf(w, f[j], acc[j]);
        }
        float mx = 0.f;
        for (int j = 0; j < 32; j++) {
            float v = fmaxf(acc[j], 0.f);
            g_feat[(bb * NPTS + base + j) * 448 + 192 + oc] = v;
            mx = fmaxf(mx, v);
        }
        atomicMax(&g_gmax[bb * 256 + oc], __float_as_int(mx));
    }
}

// ---------------- fold global feats into r1 bias ----------------
__global__ void c1_kernel(const float* __restrict__ r1, const float* __restrict__ rb1) {
    __shared__ float fms[256];
    int t = threadIdx.x;
    int bb = blockIdx.x >> 3;
    int ocbase = (blockIdx.x & 7) * 32;
    fms[t] = __int_as_float(g_gmax[bb * 256 + t]);
    __syncthreads();
    int oc = ocbase + (t >> 3);
    int seg = t & 7;
    const float* row = r1 + oc * 707 + 451 + seg * 32;
    float s = 0.f;
    #pragma unroll
    for (int i = 0; i < 32; i++) s = fmaf(row[i], fms[seg * 32 + i], s);
    s += __shfl_xor_sync(0xffffffffu, s, 1);
    s += __shfl_xor_sync(0xffffffffu, s, 2);
    s += __shfl_xor_sync(0xffffffffu, s, 4);
    if (seg == 0) g_c1[bb * 256 + oc] = s + rb1[oc];
}

// ---------------- G = feat @ W1[3:451]: per 32 points ----------------
// grid = BATCH*128, 256 threads, smem = 448*36*4 = 64512 B
__global__ void __launch_bounds__(256) gfeat_kernel() {
    extern __shared__ float fs[];   // [448][36]
    int t = threadIdx.x;
    int bb = blockIdx.x >> 7;
    int base = (blockIdx.x & 127) * 32;

    for (int idx = t; idx < 32 * 448; idx += 256) {
        int p = idx / 448, c = idx - p * 448;
        fs[c * LDQ + p] = g_feat[(size_t)(bb * NPTS + base + p) * 448 + c];
    }
    __syncthreads();

    int ocb = t & 63;
    int p2 = (t >> 6) * 8;   // 8 points per group
    ULL acc[4][4];
    #pragma unroll
    for (int j = 0; j < 4; j++)
        #pragma unroll
        for (int i = 0; i < 4; i++) acc[j][i] = 0ULL;

    const float4* wb = (const float4*)g_rG;
    float4 w0 = wb[ocb], w1 = wb[ocb + 64], w2 = wb[ocb + 128], w3 = wb[ocb + 192];
    for (int cg = 0; cg < 112; cg++) {
        int cn = (cg < 111) ? cg + 1 : cg;
        float4 n0 = wb[cn * 256 + ocb];
        float4 n1 = wb[cn * 256 + ocb + 64];
        float4 n2 = wb[cn * 256 + ocb + 128];
        float4 n3 = wb[cn * 256 + ocb + 192];
        #pragma unroll
        for (int cc = 0; cc < 4; cc++) {
            const float* arow = fs + (cg * 4 + cc) * LDQ + p2;
            ulonglong2 aA = *(const ulonglong2*)(arow);
            ulonglong2 aB = *(const ulonglong2*)(arow + 4);
            float s0 = cc == 0 ? w0.x : cc == 1 ? w0.y : cc == 2 ? w0.z : w0.w;
            float s1 = cc == 0 ? w1.x : cc == 1 ? w1.y : cc == 2 ? w1.z : w1.w;
            float s2 = cc == 0 ? w2.x : cc == 1 ? w2.y : cc == 2 ? w2.z : w2.w;
            float s3 = cc == 0 ? w3.x : cc == 1 ? w3.y : cc == 2 ? w3.z : w3.w;
            ULL v0 = pk2(s0), v1 = pk2(s1), v2 = pk2(s2), v3 = pk2(s3);
            fma2(acc[0][0], v0, aA.x); fma2(acc[0][1], v0, aA.y);
            fma2(acc[0][2], v0, aB.x); fma2(acc[0][3], v0, aB.y);
            fma2(acc[1][0], v1, aA.x); fma2(acc[1][1], v1, aA.y);
            fma2(acc[1][2], v1, aB.x); fma2(acc[1][3], v1, aB.y);
            fma2(acc[2][0], v2, aA.x); fma2(acc[2][1], v2, aA.y);
            fma2(acc[2][2], v2, aB.x); fma2(acc[2][3], v2, aB.y);
            fma2(acc[3][0], v3, aA.x); fma2(acc[3][1], v3, aA.y);
            fma2(acc[3][2], v3, aB.x); fma2(acc[3][3], v3, aB.y);
        }
        w0 = n0; w1 = n1; w2 = n2; w3 = n3;
    }

    #pragma unroll
    for (int j = 0; j < 4; j++) {
        int oc = ocb + 64 * j;
        #pragma unroll
        for (int i = 0; i < 4; i++) {
            float lo, hi; upk2(acc[j][i], lo, hi);
            g_G[(size_t)(bb * NPTS + base + p2 + 2 * i)     * 256 + oc] = lo;
            g_G[(size_t)(bb * NPTS + base + p2 + 2 * i + 1) * 256 + oc] = hi;
        }
    }
}

// ---------------- warp top-3 merge returning dists ----------------
__device__ __forceinline__ void merge3d(float b0, float b1, float b2,
                                        int i0, int i1, int i2, int lane,
                                        int sel[3], float seld[3]) {
    int j = 0;
    #pragma unroll
    for (int s = 0; s < 3; s++) {
        float cv = (j == 0) ? b0 : ((j == 1) ? b1 : ((j == 2) ? b2 : 3.4e38f));
        int   ci = (j == 0) ? i0 : ((j == 1) ? i1 : i2);
        float rv = cv; int rl = lane;
        #pragma unroll
        for (int off = 16; off; off >>= 1) {
            float ov = __shfl_down_sync(0xffffffffu, rv, off);
            int   ol = __shfl_down_sync(0xffffffffu, rl, off);
            if (ov < rv) { rv = ov; rl = ol; }
        }
        int wl = __shfl_sync(0xffffffffu, rl, 0);
        seld[s] = __shfl_sync(0xffffffffu, rv, 0);
        sel[s]  = __shfl_sync(0xffffffffu, ci, wl);
        if (lane == wl) j++;
    }
}

// ---------------- fused KNN(3) + h1 build + stages 2-4 ----------------
// smem layout (floats):
//   h1s   [0, 9216)         256*36
//   h2s   [9216, 13824)     128*36   (chunk/w1q/c1 overlay this region pre-stage2)
//   h3s   [0, 2304)          64*36   (overlays h1s after stage2)
//   chunk [9216, 10752)
//   w1qs  [10752, 11776)
//   c1s   [11776, 12032)
// total = 13824 floats = 55296 B -> 4 CTAs/SM
__global__ void __launch_bounds__(256, 4) knnreg_kernel(
        const float* __restrict__ opts, const float* __restrict__ qpts,
        const float* __restrict__ rb2, const float* __restrict__ rb3,
        const float* __restrict__ r4, const float* __restrict__ rb4,
        float* __restrict__ out) {
    extern __shared__ float sm[];
    float* h1s  = sm;
    float* h2s  = sm + 9216;
    float* h3s  = sm;
    float* cx   = sm + 9216;
    float* cy   = cx + CHUNK;
    float* cz   = cy + CHUNK;
    float* w1qs = sm + 10752;
    float* c1s  = sm + 11776;
    int t = threadIdx.x;
    int bb = blockIdx.x >> 9, tile = blockIdx.x & 511;
    int qbase = tile * 32;
    int warp = t >> 5, lane = t & 31;

    for (int i = t; i < 1024; i += 256) w1qs[i] = g_w1q[i];
    if (t < 256) c1s[t] = g_c1[bb * 256 + t];

    int q0 = qbase + warp * 4;
    float qx[4], qy[4], qz[4];
    #pragma unroll
    for (int r = 0; r < 4; r++) {
        qx[r] = qpts[bb * 3 * NQ + q0 + r];
        qy[r] = qpts[bb * 3 * NQ + NQ + q0 + r];
        qz[r] = qpts[bb * 3 * NQ + 2 * NQ + q0 + r];
    }

    float bd[4][3];
    int   bi[4][3];
    #pragma unroll
    for (int r = 0; r < 4; r++)
        #pragma unroll
        for (int s = 0; s < 3; s++) { bd[r][s] = 3.4e38f; bi[r][s] = 0; }

    const float* obase = opts + bb * 3 * NPTS;
    for (int ch = 0; ch < NPTS / CHUNK; ch++) {
        __syncthreads();
        for (int i = t; i < CHUNK; i += 256) {
            cx[i] = obase[ch * CHUNK + i];
            cy[i] = obase[NPTS + ch * CHUNK + i];
            cz[i] = obase[2 * NPTS + ch * CHUNK + i];
        }
        __syncthreads();
        int gb = ch * CHUNK;
        for (int p = lane; p < CHUNK; p += 32) {
            float x = cx[p], y = cy[p], z = cz[p];
            #pragma unroll
            for (int r = 0; r < 4; r++) {
                float dx = qx[r] - x, dy = qy[r] - y, dz = qz[r] - z;
                float dd = fmaf(dx, dx, fmaf(dy, dy, dz * dz));
                if (dd < bd[r][2]) {
                    if (dd < bd[r][1]) {
                        bd[r][2] = bd[r][1]; bi[r][2] = bi[r][1];
                        if (dd < bd[r][0]) { bd[r][1] = bd[r][0]; bi[r][1] = bi[r][0]; bd[r][0] = dd; bi[r][0] = gb + p; }
                        else               { bd[r][1] = dd; bi[r][1] = gb + p; }
                    } else { bd[r][2] = dd; bi[r][2] = gb + p; }
                }
            }
        }
    }
    __syncthreads();

    // ---- per query: weights + gather G rows -> h1 ----
    #pragma unroll
    for (int r = 0; r < 4; r++) {
        int sel[3]; float seld[3];
        merge3d(bd[r][0], bd[r][1], bd[r][2], bi[r][0], bi[r][1], bi[r][2], lane, sel, seld);
        int ql = warp * 4 + r;

        float wk0 = 1.f / (sqrtf(seld[0]) + 1e-8f);
        float wk1 = 1.f / (sqrtf(seld[1]) + 1e-8f);
        float wk2 = 1.f / (sqrtf(seld[2]) + 1e-8f);
        float inv = 1.f / (wk0 + wk1 + wk2);
        wk0 *= inv; wk1 *= inv; wk2 *= inv;

        const float4* G0 = (const float4*)(g_G + (size_t)(bb * NPTS + sel[0]) * 256);
        const float4* G1 = (const float4*)(g_G + (size_t)(bb * NPTS + sel[1]) * 256);
        const float4* G2 = (const float4*)(g_G + (size_t)(bb * NPTS + sel[2]) * 256);
        const float4* WQ = (const float4*)w1qs;
        #pragma unroll
        for (int h = 0; h < 2; h++) {
            int f4 = lane * 2 + h;
            float4 a = G0[f4], b = G1[f4], c = G2[f4];
            #pragma unroll
            for (int e = 0; e < 4; e++) {
                int oc = f4 * 4 + e;
                float4 w = WQ[oc];
                float ga = e == 0 ? a.x : e == 1 ? a.y : e == 2 ? a.z : a.w;
                float gb2 = e == 0 ? b.x : e == 1 ? b.y : e == 2 ? b.z : b.w;
                float gc = e == 0 ? c.x : e == 1 ? c.y : e == 2 ? c.z : c.w;
                float v = c1s[oc];
                v = fmaf(qx[r], w.x, v);
                v = fmaf(qy[r], w.y, v);
                v = fmaf(qz[r], w.z, v);
                v = fmaf(wk0, ga, v);
                v = fmaf(wk1, gb2, v);
                v = fmaf(wk2, gc, v);
                h1s[oc * LDQ + ql] = fmaxf(v, 0.f);
            }
        }
    }
    __syncthreads();

    int ocb = t & 63;
    int q2 = (t >> 6) * 8;

    // ---- stage 2: 256 -> 128; 2 ocs x 4 q-pairs, prefetch ----
    {
        ULL acc[2][4];
        #pragma unroll
        for (int j = 0; j < 2; j++) {
            ULL c = pk2(rb2[ocb + 64 * j]);
            #pragma unroll
            for (int i = 0; i < 4; i++) acc[j][i] = c;
        }
        const float4* wb = (const float4*)g_r2o;
        float4 w0 = wb[ocb], w1 = wb[ocb + 64];
        for (int kg = 0; kg < 64; kg++) {
            int kn = (kg < 63) ? kg + 1 : kg;
            float4 n0 = wb[kn * 128 + ocb];
            float4 n1 = wb[kn * 128 + ocb + 64];
            #pragma unroll
            for (int kk = 0; kk < 4; kk++) {
                const float* arow = h1s + (kg * 4 + kk) * LDQ + q2;
                ulonglong2 aA = *(const ulonglong2*)(arow);
                ulonglong2 aB = *(const ulonglong2*)(arow + 4);
                float s0 = kk == 0 ? w0.x : kk == 1 ? w0.y : kk == 2 ? w0.z : w0.w;
                float s1 = kk == 0 ? w1.x : kk == 1 ? w1.y : kk == 2 ? w1.z : w1.w;
                ULL v0 = pk2(s0), v1 = pk2(s1);
                fma2(acc[0][0], v0, aA.x); fma2(acc[0][1], v0, aA.y);
                fma2(acc[0][2], v0, aB.x); fma2(acc[0][3], v0, aB.y);
                fma2(acc[1][0], v1, aA.x); fma2(acc[1][1], v1, aA.y);
                fma2(acc[1][2], v1, aB.x); fma2(acc[1][3], v1, aB.y);
            }
            w0 = n0; w1 = n1;
        }
        __syncthreads();
        #pragma unroll
        for (int j = 0; j < 2; j++) {
            float* hrow = h2s + (ocb + 64 * j) * LDQ + q2;
            #pragma unroll
            for (int i = 0; i < 4; i++) {
                float lo, hi; upk2(acc[j][i], lo, hi);
                hrow[2 * i]     = fmaxf(lo, 0.f);
                hrow[2 * i + 1] = fmaxf(hi, 0.f);
            }
        }
    }
    __syncthreads();

    // ---- stage 3: 128 -> 64 (h3 overlays dead h1 region) ----
    {
        ULL acc[4];
        ULL c = pk2(rb3[ocb]);
        #pragma unroll
        for (int i = 0; i < 4; i++) acc[i] = c;
        const float4* wb = (const float4*)g_r3o;
        for (int kg = 0; kg < 32; kg++) {
            float4 w = wb[kg * 64 + ocb];
            #pragma unroll
            for (int kk = 0; kk < 4; kk++) {
                const float* arow = h2s + (kg * 4 + kk) * LDQ + q2;
                ulonglong2 aA = *(const ulonglong2*)(arow);
                ulonglong2 aB = *(const ulonglong2*)(arow + 4);
                float ws = kk == 0 ? w.x : kk == 1 ? w.y : kk == 2 ? w.z : w.w;
                ULL wv = pk2(ws);
                fma2(acc[0], wv, aA.x);
                fma2(acc[1], wv, aA.y);
                fma2(acc[2], wv, aB.x);
                fma2(acc[3], wv, aB.y);
            }
        }
        __syncthreads();   // all h1 reads done before h3 overlays
        float* hrow = h3s + ocb * LDQ + q2;
        #pragma unroll
        for (int i = 0; i < 4; i++) {
            float lo, hi; upk2(acc[i], lo, hi);
            hrow[2 * i]     = fmaxf(lo, 0.f);
            hrow[2 * i + 1] = fmaxf(hi, 0.f);
        }
    }
    __syncthreads();

    // ---- stage 4: 64 -> 1 ----
    {
        int w4 = t >> 5, l4 = t & 31;
        int qloc = w4 * 4 + (l4 >> 3);
        int c0 = l4 & 7;
        float p = 0.f;
        #pragma unroll
        for (int jj = 0; jj < 8; jj++) {
            int c = c0 + jj * 8;
            p = fmaf(r4[c], h3s[c * LDQ + qloc], p);
        }
        p += __shfl_xor_sync(0xffffffffu, p, 1);
        p += __shfl_xor_sync(0xffffffffu, p, 2);
        p += __shfl_xor_sync(0xffffffffu, p, 4);
        if ((l4 & 7) == 0) out[bb * NQ + qbase + qloc] = p + rb4[0];
    }
}

// ---------------- launch ----------------
extern "C" void kernel_launch(void* const* d_in, const int* in_sizes, int n_in,
                              void* d_out, int out_size) {
    const float* opts = (const float*)d_in[0];
    const float* qpts = (const float*)d_in[1];
    const float* w1 = (const float*)d_in[2];
    const float* b1 = (const float*)d_in[3];
    const float* w2 = (const float*)d_in[4];
    const float* b2 = (const float*)d_in[5];
    const float* w3 = (const float*)d_in[6];
    const float* b3 = (const float*)d_in[7];
    const float* r1 = (const float*)d_in[8];
    const float* rb1 = (const float*)d_in[9];
    const float* r2 = (const float*)d_in[10];
    const float* rb2 = (const float*)d_in[11];
    const float* r3 = (const float*)d_in[12];
    const float* rb3 = (const float*)d_in[13];
    const float* r4 = (const float*)d_in[14];
    const float* rb4 = (const float*)d_in[15];
    float* out = (float*)d_out;

    cudaFuncSetAttribute(feat_kernel, cudaFuncAttributeMaxDynamicSharedMemorySize, 190336);
    cudaFuncSetAttribute(gfeat_kernel, cudaFuncAttributeMaxDynamicSharedMemorySize, 64512);
    cudaFuncSetAttribute(knnreg_kernel, cudaFuncAttributeMaxDynamicSharedMemorySize, 55296);

    prep_kernel<<<64, 256>>>(r1, r2, r3);
    feat_kernel<<<BATCH * (NPTS / 32), 256, 190336>>>(opts, w1, b1, w2, b2, w3, b3);
    c1_kernel<<<BATCH * 8, 256>>>(r1, rb1);
    gfeat_kernel<<<BATCH * 128, 256, 64512>>>();
    knnreg_kernel<<<BATCH * (NQ / 32), 256, 55296>>>(opts, qpts, rb2, rb3, r4, rb4, out);
}